// round 15
// baseline (speedup 1.0000x reference)
#include <cuda_runtime.h>
#include <cstdint>

#define NB  32
#define NC  192
#define NL  4096
#define CPB 2                  // channels per gather block
#define NCB (NC / CPB)         // 96 channel-groups per batch
#define GBLK (NB * NCB)        // 3072 blocks
#define GT  512                // threads per block

// Scratch (no dynamic allocation allowed; zero-initialized at load)
__device__ int   g_order[NB * NL];   // always-valid token ids 0..NL-1
__device__ int   g_count[NB];
__device__ float g_theta[NB];
__device__ int   g_flag;             // stats-complete arrivals (reset each run)
__device__ int   g_done;             // gather-complete ticket   (reset each run)

// ---------------------------------------------------------------------------
// Fused kernel. Blocks 0..NB-1 first compute stats+compaction for batch=blk
// and arrive on g_flag. ALL blocks stage their x-tile to SMEM (DRAM reads in
// flight during stats), spin until g_flag==NB, then gather. Last block resets
// the counters for graph-replay determinism. Block 0 writes the two scalars.
// ---------------------------------------------------------------------------
__global__ __launch_bounds__(GT) void fused_kernel(const float* __restrict__ x,
                                                   const float* __restrict__ delta,
                                                   float* __restrict__ y,
                                                   float* __restrict__ out_kr,
                                                   float* __restrict__ out_tm)
{
    __shared__ float  sx[CPB * NL];          // 32 KB
    __shared__ float  smn[16], smx[16];
    __shared__ double ssum[16], ssq[16];
    __shared__ int    wsum[16];
    __shared__ float  s_lo, s_rng, s_theta;

    const int blk  = blockIdx.x;
    const int tid  = threadIdx.x;
    const int lane = tid & 31;
    const int warp = tid >> 5;               // 16 warps
    const int b    = blk / NCB;
    const int c0   = (blk % NCB) * CPB;
    const size_t base = ((size_t)b * NC + c0) * NL;

    // ---- Producer role: blocks 0..NB-1 compute stats for batch = blk ----
    if (blk < NB) {
        const float4* dp = reinterpret_cast<const float4*>(delta + (size_t)blk * NL) + tid * 2;
        float4 d0 = dp[0], d1 = dp[1];
        float a[8] = { fabsf(d0.x), fabsf(d0.y), fabsf(d0.z), fabsf(d0.w),
                       fabsf(d1.x), fabsf(d1.y), fabsf(d1.z), fabsf(d1.w) };

        float mn = a[0], mx = a[0];
        double s0 = 0.0, s1 = 0.0, q0 = 0.0, q1 = 0.0;
        #pragma unroll
        for (int i = 0; i < 4; i++) {
            mn = fminf(mn, fminf(a[2*i], a[2*i+1]));
            mx = fmaxf(mx, fmaxf(a[2*i], a[2*i+1]));
            double e0 = (double)a[2*i], e1 = (double)a[2*i+1];
            s0 += e0; q0 += e0 * e0;
            s1 += e1; q1 += e1 * e1;
        }
        double s = s0 + s1, q = q0 + q1;

        #pragma unroll
        for (int o = 16; o; o >>= 1) {
            mn = fminf(mn, __shfl_xor_sync(0xffffffffu, mn, o));
            mx = fmaxf(mx, __shfl_xor_sync(0xffffffffu, mx, o));
            s += __shfl_xor_sync(0xffffffffu, s, o);
            q += __shfl_xor_sync(0xffffffffu, q, o);
        }
        if (lane == 0) { smn[warp] = mn; smx[warp] = mx; ssum[warp] = s; ssq[warp] = q; }
        __syncthreads();

        if (warp == 0) {
            mn = (lane < 16) ? smn[lane] :  1e30f;
            mx = (lane < 16) ? smx[lane] : -1e30f;
            s  = (lane < 16) ? ssum[lane] : 0.0;
            q  = (lane < 16) ? ssq[lane]  : 0.0;
            #pragma unroll
            for (int o = 8; o; o >>= 1) {
                mn = fminf(mn, __shfl_xor_sync(0xffffffffu, mn, o));
                mx = fmaxf(mx, __shfl_xor_sync(0xffffffffu, mx, o));
                s += __shfl_xor_sync(0xffffffffu, s, o);
                q += __shfl_xor_sync(0xffffffffu, q, o);
            }
            if (lane == 0) {
                float lo  = mn;
                float rng = fmaxf(mx - lo, 1e-3f);
                double mu_a  = s / (double)NL;
                double var_a = (q - s * s / (double)NL) / (double)(NL - 1);
                if (var_a < 0.0) var_a = 0.0;
                s_lo = lo; s_rng = rng;
                s_theta = (float)((mu_a - (double)lo) / (double)rng
                                  - 0.1 * sqrt(var_a) / (double)rng);
            }
        }
        __syncthreads();

        const float lo = s_lo, rng = s_rng, theta = s_theta;
        unsigned kbits = 0;
        int local = 0;
        #pragma unroll
        for (int i = 0; i < 8; i++) {
            float imp = (a[i] - lo) / rng;
            if (imp >= theta) { kbits |= (1u << i); local++; }
        }

        int incl = local;
        #pragma unroll
        for (int o = 1; o < 32; o <<= 1) {
            int t = __shfl_up_sync(0xffffffffu, incl, o);
            if (lane >= o) incl += t;
        }
        if (lane == 31) wsum[warp] = incl;
        __syncthreads();
        if (warp == 0) {
            int t = (lane < 16) ? wsum[lane] : 0;
            #pragma unroll
            for (int o = 1; o < 16; o <<= 1) {
                int u = __shfl_up_sync(0xffffffffu, t, o);
                if (lane >= o) t += u;
            }
            if (lane < 16) wsum[lane] = t;
        }
        __syncthreads();

        int pos   = (warp ? wsum[warp - 1] : 0) + (incl - local);
        int obase = blk * NL;
        const int l = tid * 8;
        #pragma unroll
        for (int i = 0; i < 8; i++) {
            if (kbits & (1u << i)) g_order[obase + pos++] = l + i;
        }
        // No tail fill: stale entries are always valid ids; gather predicates
        // positions j >= cnt to 0.0f.

        __syncthreads();
        if (tid == 0) {
            g_count[blk] = wsum[15];
            g_theta[blk] = theta;
            __threadfence();                     // publish before arrival
            atomicAdd(&g_flag, 1);
        }
    }

    // ---- Stage x-tile to SMEM (DRAM reads overlap stats elsewhere) ----
    const float4* xp = reinterpret_cast<const float4*>(x + base);
    #pragma unroll
    for (int i = 0; i < CPB * NL / 4 / GT; i++)
        reinterpret_cast<float4*>(sx)[tid + GT * i] = xp[tid + GT * i];

    // ---- Wait for all batch stats ----
    if (tid == 0) {
        while (*((volatile int*)&g_flag) != NB) __nanosleep(64);
        __threadfence();                         // acquire
    }
    __syncthreads();                             // also covers staging

    // ---- Gather ----
    const int4* op = reinterpret_cast<const int4*>(g_order + b * NL);
    const int4 o0 = op[2 * tid];
    const int4 o1 = op[2 * tid + 1];
    const int  cnt = g_count[b];

    const int j = 8 * tid;
    #pragma unroll
    for (int r = 0; r < CPB; r++) {
        const float* sr = sx + r * NL;
        float4 r0, r1;
        r0.x = (j     < cnt) ? sr[o0.x] : 0.0f;
        r0.y = (j + 1 < cnt) ? sr[o0.y] : 0.0f;
        r0.z = (j + 2 < cnt) ? sr[o0.z] : 0.0f;
        r0.w = (j + 3 < cnt) ? sr[o0.w] : 0.0f;
        r1.x = (j + 4 < cnt) ? sr[o1.x] : 0.0f;
        r1.y = (j + 5 < cnt) ? sr[o1.y] : 0.0f;
        r1.z = (j + 6 < cnt) ? sr[o1.z] : 0.0f;
        r1.w = (j + 7 < cnt) ? sr[o1.w] : 0.0f;
        float4* yp = reinterpret_cast<float4*>(y + base + (size_t)r * NL) + 2 * tid;
        yp[0] = r0;
        yp[1] = r1;
    }

    // ---- Scalars (block 0, after flag: all g_* valid) ----
    if (blk == 0 && tid < 32) {
        float cntf = (float)g_count[tid];
        float th   = g_theta[tid];
        #pragma unroll
        for (int o2 = 16; o2; o2 >>= 1) {
            cntf += __shfl_xor_sync(0xffffffffu, cntf, o2);
            th   += __shfl_xor_sync(0xffffffffu, th,   o2);
        }
        if (tid == 0) {
            *out_kr = (cntf / (float)NB) / (float)NL;
            *out_tm = th / (float)NB;
        }
    }

    // ---- Replay-safe counter reset by the last-finishing block ----
    if (tid == 0) {
        __threadfence();
        int d = atomicAdd(&g_done, 1);
        if (d == GBLK - 1) {
            atomicExch(&g_flag, 0);
            atomicExch(&g_done, 0);
        }
    }
}

extern "C" void kernel_launch(void* const* d_in, const int* in_sizes, int n_in,
                              void* d_out, int out_size)
{
    const float* x     = (const float*)d_in[0];   // [32,192,64,64]
    const float* delta = (const float*)d_in[1];   // [32,1,64,64]
    float* out = (float*)d_out;

    fused_kernel<<<GBLK, GT>>>(x, delta, out,
                               out + (out_size - 2), out + (out_size - 1));
}